// round 8
// baseline (speedup 1.0000x reference)
#include <cuda_runtime.h>
#include <cstdint>

#define BB 8192
#define FF 32
#define EE 64
#define PP 496   // 32 choose 2
#define GRID 592 // 148 SMs x 4 resident CTAs

__device__ __forceinline__ void cp_async16(uint32_t dst, const float4* src) {
    asm volatile("cp.async.cg.shared.global [%0], [%1], 16;" :: "r"(dst), "l"(src));
}

template<int P0>
__device__ __forceinline__ void store_group(const float (&xwc)[FF],
                                            const float (&xc)[FF],
                                            float* __restrict__ outb)
{
    #pragma unroll
    for (int i = 0; i < FF - 1; i++) {
        #pragma unroll
        for (int j = i + 1; j < FF; j++) {
            const int p = i * (2 * FF - 1 - i) / 2 + (j - i - 1);
            if (p >= P0 && p < P0 + PP / 4) {
                // streaming scalar store: 32 consecutive d-lanes -> 128B coalesced
                __stcs(outb + p * EE, xwc[i] * xc[j]);
            }
        }
    }
}

__global__ __launch_bounds__(256, 4)
void bilinear_pair_kernel(const float* __restrict__ x,
                          const float* __restrict__ W,
                          float* __restrict__ out)
{
    __shared__ float Ws[EE * EE];        // 16 KB  W, loaded ONCE per CTA
    __shared__ float xsb[2][FF * EE];    // 2x8 KB double-buffered x[b]
    __shared__ float xws[FF * EE];       // 8 KB   (x[b] @ W)

    const int tid = threadIdx.x;

    // ---- load W once ----
    {
        const float4* W4  = (const float4*)W;
        float4*       Ws4 = (float4*)Ws;
        #pragma unroll
        for (int k = tid; k < EE * EE / 4; k += 256)
            Ws4[k] = W4[k];
    }

    const uint32_t xs_s0 = (uint32_t)__cvta_generic_to_shared(&xsb[0][0]);
    const uint32_t xs_s1 = (uint32_t)__cvta_generic_to_shared(&xsb[1][0]);

    // ---- prefetch first x[b] ----
    int b = blockIdx.x;
    {
        const float4* src = (const float4*)(x + (size_t)b * FF * EE);
        cp_async16(xs_s0 + tid * 16, src + tid);
        cp_async16(xs_s0 + (tid + 256) * 16, src + tid + 256);
        asm volatile("cp.async.commit_group;");
    }

    int cur = 0;
    for (; b < BB; b += GRID) {
        asm volatile("cp.async.wait_group 0;");
        __syncthreads();                 // xs[cur] ready; xws readers of prev iter done

        // ---- prefetch next x during matmul + store ----
        if (b + GRID < BB) {
            const float4* src = (const float4*)(x + (size_t)(b + GRID) * FF * EE);
            const uint32_t dst = cur ? xs_s0 : xs_s1;
            cp_async16(dst + tid * 16, src + tid);
            cp_async16(dst + (tid + 256) * 16, src + tid + 256);
            asm volatile("cp.async.commit_group;");
        }

        const float* xs = xsb[cur];

        // ---- matmul: thread = 2 rows x 4 cols register tile ----
        {
            const int r0 = (tid >> 4) * 2;
            const int c4 = (tid & 15) * 4;
            float4 acc0 = make_float4(0.f, 0.f, 0.f, 0.f);
            float4 acc1 = make_float4(0.f, 0.f, 0.f, 0.f);

            #pragma unroll 16
            for (int e = 0; e < EE; e++) {
                float4 w  = *(const float4*)(Ws + e * EE + c4);
                float  a0 = xs[r0 * EE + e];
                float  a1 = xs[(r0 + 1) * EE + e];
                acc0.x = fmaf(a0, w.x, acc0.x);
                acc0.y = fmaf(a0, w.y, acc0.y);
                acc0.z = fmaf(a0, w.z, acc0.z);
                acc0.w = fmaf(a0, w.w, acc0.w);
                acc1.x = fmaf(a1, w.x, acc1.x);
                acc1.y = fmaf(a1, w.y, acc1.y);
                acc1.z = fmaf(a1, w.z, acc1.z);
                acc1.w = fmaf(a1, w.w, acc1.w);
            }
            *(float4*)(xws + r0 * EE + c4)       = acc0;
            *(float4*)(xws + (r0 + 1) * EE + c4) = acc1;
        }
        __syncthreads();                 // xws ready

        // ---- store phase: thread owns column d, group g owns 124 pairs ----
        {
            const int d = tid & 63;
            const int g = tid >> 6;

            float xc[FF];
            float xwc[FF];
            #pragma unroll
            for (int f = 0; f < FF; f++) {
                xc[f]  = xs[f * EE + d];
                xwc[f] = xws[f * EE + d];
            }

            float* outb = out + (size_t)b * PP * EE + d;

            switch (g) {
                case 0: store_group<0>(xwc, xc, outb); break;
                case 1: store_group<124>(xwc, xc, outb); break;
                case 2: store_group<248>(xwc, xc, outb); break;
                default: store_group<372>(xwc, xc, outb); break;
            }
        }
        cur ^= 1;
    }
}

extern "C" void kernel_launch(void* const* d_in, const int* in_sizes, int n_in,
                              void* d_out, int out_size)
{
    const float* x = (const float*)d_in[0];
    const float* W = (const float*)d_in[1];
    float*       o = (float*)d_out;
    bilinear_pair_kernel<<<GRID, 256>>>(x, W, o);
}